// round 1
// baseline (speedup 1.0000x reference)
#include <cuda_runtime.h>
#include <cstdint>

// Problem constants (fixed by the registry problem)
#define N_TOK   262144
#define TOPK    2
#define NSLOTS  (N_TOK * TOPK)          // 524288
#define D       128                      // d_in == d_out == 128
#define NEXP    8
#define TS      128                      // slots per CTA tile

// ---- device scratch (no runtime allocation allowed) ----
__device__ float g_yscat[(size_t)NSLOTS * D];   // gated per-slot outputs, flat-slot order (256 MiB)
__device__ float g_wt[NEXP * D * D];            // WT[e][i][o] = weight[e][o][i]
__device__ int   g_seg[NEXP + 1];               // expert segment boundaries in sorted order

// -------------------------------------------------------------------
// Kernel 1: transpose weights once per launch: g_wt[e][i][o] = w[e][o][i]
// -------------------------------------------------------------------
__global__ void wt_transpose_kernel(const float* __restrict__ w) {
    __shared__ float tile[D][D + 1];
    int e = blockIdx.x;
    const float* we = w + (size_t)e * D * D;
    for (int idx = threadIdx.x; idx < D * D; idx += blockDim.x) {
        tile[idx >> 7][idx & 127] = we[idx];            // coalesced read
    }
    __syncthreads();
    float* wte = g_wt + (size_t)e * D * D;
    for (int idx = threadIdx.x; idx < D * D; idx += blockDim.x) {
        int i = idx >> 7, o = idx & 127;
        wte[idx] = tile[o][i];                          // coalesced write
    }
}

// -------------------------------------------------------------------
// Kernel 2: binary-search expert segment boundaries in sorted_expert_idxs
// -------------------------------------------------------------------
__global__ void seg_kernel(const int* __restrict__ sei) {
    int e = threadIdx.x;
    if (e > NEXP) return;
    int lo = 0, hi = NSLOTS;
    while (lo < hi) {
        int mid = (lo + hi) >> 1;
        if (sei[mid] < e) lo = mid + 1; else hi = mid;
    }
    g_seg[e] = lo;
}

// -------------------------------------------------------------------
// Kernel 3: main — per expert segment, tiles of 128 sorted slots.
// SMEM-resident transposed weight, 8x8 register tile per thread,
// gated STG.128 scatter into g_yscat (flat slot order, each slot unique).
// -------------------------------------------------------------------
#define XROW 132   // padded row stride (floats); 132*4=528 B, multiple of 16 -> float4 OK
#define SMEM_FLOATS (2 * D * XROW + 2 * TS)
#define SMEM_BYTES  (SMEM_FLOATS * 4)

extern "C" __global__ void __launch_bounds__(256, 1)
moe_main_kernel(const float* __restrict__ x,
                const float* __restrict__ gates,
                const int*   __restrict__ ssi) {
    int e    = blockIdx.y;
    int seg0 = g_seg[e];
    int seg1 = g_seg[e + 1];
    int s0   = seg0 + blockIdx.x * TS;
    if (s0 >= seg1) return;
    int cnt = min(TS, seg1 - s0);

    extern __shared__ float smem[];
    float* Wt   = smem;                 // [128][XROW] : Wt[i][o]
    float* Xs   = smem + D * XROW;      // [128][XROW] : Xs[j][i]
    float* sh_g = Xs + D * XROW;        // [TS]
    int*   sh_f = (int*)(sh_g + TS);    // [TS]

    int tid = threadIdx.x;

    // stage slot metadata (flat slot id + gate); pad with f=0, g=0 (guarded at store)
    if (tid < TS) {
        int f = 0; float g = 0.f;
        if (tid < cnt) {
            f = ssi[s0 + tid];
            g = gates[f];               // gates is [N, k] row-major -> flat index == f
        }
        sh_f[tid] = f;
        sh_g[tid] = g;
    }
    __syncthreads();

    // stage transposed weight: coalesced global read, conflict-free STS
    {
        const float* wte = g_wt + (size_t)e * D * D;
        for (int idx = tid; idx < D * D; idx += 256) {
            Wt[(idx >> 7) * XROW + (idx & 127)] = wte[idx];
        }
    }
    // stage X rows (gather): one warp per slot row, float4 coalesced
    {
        const float4* x4 = (const float4*)x;
        for (int l = tid; l < TS * 32; l += 256) {
            int j  = l >> 5;
            int i4 = l & 31;
            int tok = sh_f[j] >> 1;     // TOPK == 2
            float4 v = x4[(size_t)tok * 32 + i4];
            *(float4*)&Xs[j * XROW + i4 * 4] = v;
        }
    }
    __syncthreads();

    // 8x8 register tile: thread (tx,ty) -> dims d0..d0+7, slots j0..j0+7
    int tx = tid & 15, ty = tid >> 4;
    int d0 = tx << 3,  j0 = ty << 3;

    float acc[8][8];
#pragma unroll
    for (int r = 0; r < 8; r++)
#pragma unroll
        for (int c = 0; c < 8; c++) acc[r][c] = 0.f;

#pragma unroll 1
    for (int i = 0; i < D; i += 4) {
        float4 xa[8];
#pragma unroll
        for (int r = 0; r < 8; r++)
            xa[r] = *(const float4*)&Xs[(j0 + r) * XROW + i];
#pragma unroll
        for (int q = 0; q < 4; q++) {
            float4 wa = *(const float4*)&Wt[(i + q) * XROW + d0];
            float4 wb = *(const float4*)&Wt[(i + q) * XROW + d0 + 4];
#pragma unroll
            for (int r = 0; r < 8; r++) {
                float xv = ((const float*)&xa[r])[q];
                acc[r][0] += xv * wa.x;
                acc[r][1] += xv * wa.y;
                acc[r][2] += xv * wa.z;
                acc[r][3] += xv * wa.w;
                acc[r][4] += xv * wb.x;
                acc[r][5] += xv * wb.y;
                acc[r][6] += xv * wb.z;
                acc[r][7] += xv * wb.w;
            }
        }
    }

    // epilogue: gated scatter to flat-slot scratch (each flat slot written exactly once)
#pragma unroll
    for (int r = 0; r < 8; r++) {
        int j = j0 + r;
        if (j < cnt) {
            float g = sh_g[j];
            float* dst = g_yscat + (size_t)sh_f[j] * D + d0;
            float4 v0 = make_float4(acc[r][0] * g, acc[r][1] * g, acc[r][2] * g, acc[r][3] * g);
            float4 v1 = make_float4(acc[r][4] * g, acc[r][5] * g, acc[r][6] * g, acc[r][7] * g);
            *(float4*)(dst)     = v0;
            *(float4*)(dst + 4) = v1;
        }
    }
}

// -------------------------------------------------------------------
// Kernel 4: combine the two gated slot outputs per token (fully coalesced)
// -------------------------------------------------------------------
__global__ void combine_kernel(float* __restrict__ out) {
    size_t idx = (size_t)blockIdx.x * blockDim.x + threadIdx.x;  // float4 index, N_TOK*D/4 total
    const float4* y4 = (const float4*)g_yscat;
    size_t n  = idx >> 5;          // token
    int    d4 = (int)(idx & 31);   // float4 within row
    float4 a = y4[n * 64 + d4];
    float4 b = y4[n * 64 + 32 + d4];
    float4 r = make_float4(a.x + b.x, a.y + b.y, a.z + b.z, a.w + b.w);
    ((float4*)out)[idx] = r;
}

// -------------------------------------------------------------------
extern "C" void kernel_launch(void* const* d_in, const int* in_sizes, int n_in,
                              void* d_out, int out_size) {
    const float* inputs = (const float*)d_in[0];
    const float* weight = (const float*)d_in[1];   // [E, D_OUT, D_IN]
    const float* gates  = (const float*)d_in[2];   // [N, k]
    // d_in[3] = k (device scalar, fixed = 2 for this problem)
    const int* sei = (const int*)d_in[4];          // sorted_expert_idxs
    const int* ssi = (const int*)d_in[5];          // sorted_scattered_idxs
    float* out = (float*)d_out;

    cudaFuncSetAttribute(moe_main_kernel,
                         cudaFuncAttributeMaxDynamicSharedMemorySize, SMEM_BYTES);

    wt_transpose_kernel<<<NEXP, 256>>>(weight);
    seg_kernel<<<1, 32>>>(sei);

    dim3 grid((NSLOTS + TS - 1) / TS, NEXP);       // worst case: one expert owns everything
    moe_main_kernel<<<grid, 256, SMEM_BYTES>>>(inputs, gates, ssi);

    combine_kernel<<<(N_TOK * D / 4) / 256, 256>>>(out);
}

// round 3
// speedup vs baseline: 2.1063x; 2.1063x over previous
#include <cuda_runtime.h>
#include <cuda_bf16.h>
#include <cstdint>

// ---------------- problem constants ----------------
#define N_TOK   262144
#define TOPK    2
#define NSLOTS  (N_TOK * TOPK)     // 524288
#define D       128
#define NEXP    8
#define TS      128                // slots per tile
#define MAXTILES (NSLOTS / TS + NEXP)   // 4104

// ---------------- device scratch ----------------
__device__ float g_yscat[(size_t)NSLOTS * D];    // gated per-slot outputs (256 MiB)
__device__ uint4 g_whp[NEXP * 2048];             // W hi bf16, packed [e][out][k] (32KB/expert)
__device__ uint4 g_wlp[NEXP * 2048];             // W lo bf16, packed
__device__ int   g_seg[NEXP + 1];
__device__ int   g_tile_e[MAXTILES];
__device__ int   g_tile_s[MAXTILES];
__device__ int   g_ntiles;

// ---------------- helpers ----------------
__device__ __forceinline__ uint32_t smem_u32(const void* p) {
    uint32_t a;
    asm("{ .reg .u64 t; cvta.to.shared.u64 t, %1; cvt.u32.u64 %0, t; }" : "=r"(a) : "l"(p));
    return a;
}

__device__ __forceinline__ void ldsm_x4(uint32_t* r, uint32_t addr) {
    asm volatile("ldmatrix.sync.aligned.m8n8.x4.shared.b16 {%0,%1,%2,%3}, [%4];"
        : "=r"(r[0]), "=r"(r[1]), "=r"(r[2]), "=r"(r[3]) : "r"(addr));
}

__device__ __forceinline__ void mma_bf16(float* c, const uint32_t* a, uint32_t b0, uint32_t b1) {
    asm volatile("mma.sync.aligned.m16n8k16.row.col.f32.bf16.bf16.f32 "
        "{%0,%1,%2,%3}, {%4,%5,%6,%7}, {%8,%9}, {%0,%1,%2,%3};"
        : "+f"(c[0]), "+f"(c[1]), "+f"(c[2]), "+f"(c[3])
        : "r"(a[0]), "r"(a[1]), "r"(a[2]), "r"(a[3]), "r"(b0), "r"(b1));
}

// convert 8 fp32 -> hi/lo bf16 packs (16 B each)
__device__ __forceinline__ void cvt8(const float* v, uint4& hv, uint4& lv) {
    __nv_bfloat16 h[8]; float l[8];
#pragma unroll
    for (int i = 0; i < 8; i++) {
        h[i] = __float2bfloat16_rn(v[i]);
        l[i] = v[i] - __bfloat162float(h[i]);
    }
    uint32_t hu[4], lu[4];
#pragma unroll
    for (int i = 0; i < 4; i++) {
        __nv_bfloat162 hp = __halves2bfloat162(h[2 * i], h[2 * i + 1]);
        hu[i] = *reinterpret_cast<uint32_t*>(&hp);
        __nv_bfloat162 lp = __floats2bfloat162_rn(l[2 * i], l[2 * i + 1]);
        lu[i] = *reinterpret_cast<uint32_t*>(&lp);
    }
    hv = make_uint4(hu[0], hu[1], hu[2], hu[3]);
    lv = make_uint4(lu[0], lu[1], lu[2], lu[3]);
}

// -------------------------------------------------------------------
// Prologue 1: weight fp32 [E, d_out, d_in] -> packed bf16 hi/lo
// -------------------------------------------------------------------
__global__ void wconv_kernel(const float* __restrict__ w) {
    int e = blockIdx.x;
    int tid = threadIdx.x;
    int row = tid >> 1;        // d_out row
    int half = tid & 1;
    const float* wr = w + ((size_t)e * D + row) * D;
    uint4* whe = g_whp + e * 2048;
    uint4* wle = g_wlp + e * 2048;
#pragma unroll
    for (int g = 0; g < 8; g++) {
        int col0 = half * 64 + g * 8;
        float v[8];
#pragma unroll
        for (int i = 0; i < 8; i++) v[i] = wr[col0 + i];
        uint4 hv, lv;
        cvt8(v, hv, lv);
        int idx = row * 16 + half * 8 + g;
        whe[idx] = hv;
        wle[idx] = lv;
    }
}

// -------------------------------------------------------------------
// Prologue 2: expert segments + dense tile map
// -------------------------------------------------------------------
__global__ void seg_kernel(const int* __restrict__ sei) {
    __shared__ int seg[NEXP + 1];
    __shared__ int cnts[NEXP];
    int t = threadIdx.x;
    if (t <= NEXP) {
        int lo = 0, hi = NSLOTS;
        while (lo < hi) {
            int mid = (lo + hi) >> 1;
            if (sei[mid] < t) lo = mid + 1; else hi = mid;
        }
        seg[t] = lo;
        g_seg[t] = lo;
    }
    __syncthreads();
    if (t < NEXP) cnts[t] = (seg[t + 1] - seg[t] + TS - 1) / TS;
    __syncthreads();
    if (t < NEXP) {
        int off = 0;
        for (int i = 0; i < t; i++) off += cnts[i];
        int s = seg[t];
        for (int i = 0; i < cnts[t]; i++) {
            g_tile_e[off + i] = t;
            g_tile_s[off + i] = s + i * TS;
        }
    }
    if (t == 0) {
        int tot = 0;
        for (int i = 0; i < NEXP; i++) tot += cnts[i];
        g_ntiles = tot;
    }
}

// -------------------------------------------------------------------
// Main: bf16-split HMMA GEMM per 128-slot tile
// SMEM images: bf16 [128 rows][128 cols], row stride 272 B (conflict-free LDSM)
// -------------------------------------------------------------------
#define XROWB 272
#define IMGB  (128 * XROWB)        // 34816
#define OFF_SHF 0
#define OFF_SHG 512
#define OFF_XH  1024
#define OFF_XL  (OFF_XH + IMGB)
#define OFF_WH  (OFF_XL + IMGB)
#define OFF_WL  (OFF_WH + IMGB)
#define SMEM_TOTAL (OFF_WL + IMGB) // 140288

extern "C" __global__ void __launch_bounds__(256, 1)
moe_mma_kernel(const float* __restrict__ x,
               const float* __restrict__ gates,
               const int*   __restrict__ ssi) {
    int t = blockIdx.x;
    if (t >= g_ntiles) return;
    int e  = g_tile_e[t];
    int s0 = g_tile_s[t];
    int cnt = min(TS, g_seg[e + 1] - s0);

    extern __shared__ char smem[];
    uint32_t sb = smem_u32(smem);
    int*   sh_f = (int*)(smem + OFF_SHF);
    float* sh_g = (float*)(smem + OFF_SHG);

    int tid = threadIdx.x;
    int wid = tid >> 5;
    int lane = tid & 31;

    // ---- stage slot metadata ----
    if (tid < TS) {
        int f = 0; float g = 0.f;
        if (tid < cnt) {
            f = ssi[s0 + tid];
            g = gates[f];
        }
        sh_f[tid] = f;
        sh_g[tid] = g;
    }
    __syncthreads();   // sh_f needed by X gather below

    // ---- stage W (linear copy from packed hi/lo, coalesced) ----
    {
        const uint4* whe = g_whp + e * 2048;
        const uint4* wle = g_wlp + e * 2048;
#pragma unroll
        for (int i = 0; i < 8; i++) {
            int cid = tid + 256 * i;           // 16B chunk id, 2048 total
            int row = cid >> 4;
            int w16 = cid & 15;
            uint32_t doff = row * XROWB + w16 * 16;
            *(uint4*)(smem + OFF_WH + doff) = whe[cid];
            *(uint4*)(smem + OFF_WL + doff) = wle[cid];
        }
    }
    // ---- stage X (gather fp32, split to bf16 hi/lo) ----
    {
        int row = tid >> 1;
        int half = tid & 1;
        int tok = sh_f[row] >> 1;              // TOPK == 2
        const float4* xr = (const float4*)x + (size_t)tok * 32 + half * 16;
        char* xh = smem + OFF_XH;
        char* xl = smem + OFF_XL;
#pragma unroll
        for (int g = 0; g < 8; g++) {
            float4 a = xr[g * 2];
            float4 b = xr[g * 2 + 1];
            float v[8] = {a.x, a.y, a.z, a.w, b.x, b.y, b.z, b.w};
            uint4 hv, lv;
            cvt8(v, hv, lv);
            uint32_t off = row * XROWB + (half * 64 + g * 8) * 2;
            *(uint4*)(xh + off) = hv;
            *(uint4*)(xl + off) = lv;
        }
    }
    __syncthreads();

    // ---- warp tiles: wr in 0..3 (32 slots), wc in 0..1 (64 outs) ----
    int wr = wid & 3;
    int wc = wid >> 2;

    int lrow = (lane & 7) | (lane & 8);        // 0..15
    int kby  = (lane >> 4) * 16;               // byte offset within k16 chunk
    uint32_t aA = sb + OFF_XH + (uint32_t)(wr * 32 + lrow) * XROWB + kby;
    uint32_t aB = sb + OFF_WH + (uint32_t)(wc * 64 + lrow) * XROWB + kby;
    const uint32_t DL = IMGB;                  // hi -> lo image delta

    float acc[2][8][4];
#pragma unroll
    for (int mt = 0; mt < 2; mt++)
#pragma unroll
        for (int nt = 0; nt < 8; nt++)
#pragma unroll
            for (int i = 0; i < 4; i++) acc[mt][nt][i] = 0.f;

#pragma unroll
    for (int kk = 0; kk < 8; kk++) {
        uint32_t kb = kk * 32;
        uint32_t ah[2][4], al[2][4];
        ldsm_x4(ah[0], aA + kb);
        ldsm_x4(ah[1], aA + 16 * XROWB + kb);
        ldsm_x4(al[0], aA + DL + kb);
        ldsm_x4(al[1], aA + DL + 16 * XROWB + kb);
#pragma unroll
        for (int ng = 0; ng < 4; ng++) {
            uint32_t bh[4], bl[4];
            ldsm_x4(bh, aB + ng * 16 * XROWB + kb);
            ldsm_x4(bl, aB + DL + ng * 16 * XROWB + kb);
#pragma unroll
            for (int mt = 0; mt < 2; mt++) {
                mma_bf16(acc[mt][2 * ng],     ah[mt], bh[0], bh[2]);
                mma_bf16(acc[mt][2 * ng + 1], ah[mt], bh[1], bh[3]);
                mma_bf16(acc[mt][2 * ng],     al[mt], bh[0], bh[2]);
                mma_bf16(acc[mt][2 * ng + 1], al[mt], bh[1], bh[3]);
                mma_bf16(acc[mt][2 * ng],     ah[mt], bl[0], bl[2]);
                mma_bf16(acc[mt][2 * ng + 1], ah[mt], bl[1], bl[3]);
            }
        }
    }

    // ---- epilogue: gate + scatter (float2 per frag-pair) ----
    {
        int row_lo = lane >> 2;
        int col0 = wc * 64 + (lane & 3) * 2;
#pragma unroll
        for (int mt = 0; mt < 2; mt++) {
            int ja = wr * 32 + mt * 16 + row_lo;
            int jb = ja + 8;
            bool oka = ja < cnt, okb = jb < cnt;
            float ga = sh_g[ja], gb = sh_g[jb];
            float* da = g_yscat + (size_t)sh_f[ja] * D + col0;
            float* db = g_yscat + (size_t)sh_f[jb] * D + col0;
#pragma unroll
            for (int nt = 0; nt < 8; nt++) {
                if (oka) {
                    float2 v = make_float2(acc[mt][nt][0] * ga, acc[mt][nt][1] * ga);
                    *(float2*)(da + nt * 8) = v;
                }
                if (okb) {
                    float2 v = make_float2(acc[mt][nt][2] * gb, acc[mt][nt][3] * gb);
                    *(float2*)(db + nt * 8) = v;
                }
            }
        }
    }
}

// -------------------------------------------------------------------
// combine: out[n] = y[2n] + y[2n+1]  (near DRAM roofline already)
// -------------------------------------------------------------------
__global__ void combine_kernel(float* __restrict__ out) {
    size_t idx = (size_t)blockIdx.x * blockDim.x + threadIdx.x;
    const float4* y4 = (const float4*)g_yscat;
    size_t n = idx >> 5;
    int d4 = (int)(idx & 31);
    float4 a = y4[n * 64 + d4];
    float4 b = y4[n * 64 + 32 + d4];
    ((float4*)out)[idx] = make_float4(a.x + b.x, a.y + b.y, a.z + b.z, a.w + b.w);
}

// -------------------------------------------------------------------
extern "C" void kernel_launch(void* const* d_in, const int* in_sizes, int n_in,
                              void* d_out, int out_size) {
    const float* inputs = (const float*)d_in[0];
    const float* weight = (const float*)d_in[1];
    const float* gates  = (const float*)d_in[2];
    const int*   sei    = (const int*)d_in[4];
    const int*   ssi    = (const int*)d_in[5];
    float* out = (float*)d_out;

    cudaFuncSetAttribute(moe_mma_kernel,
                         cudaFuncAttributeMaxDynamicSharedMemorySize, SMEM_TOTAL);

    wconv_kernel<<<NEXP, 256>>>(weight);
    seg_kernel<<<1, 32>>>(sei);

    moe_mma_kernel<<<MAXTILES, 256, SMEM_TOTAL>>>(inputs, gates, ssi);

    combine_kernel<<<(N_TOK * D / 4) / 256, 256>>>(out);
}

// round 4
// speedup vs baseline: 2.4315x; 1.1544x over previous
#include <cuda_runtime.h>
#include <cuda_bf16.h>
#include <cstdint>

// ---------------- problem constants ----------------
#define N_TOK   262144
#define TOPK    2
#define NSLOTS  (N_TOK * TOPK)     // 524288
#define D       128
#define NEXP    8
#define TS      128                // slots per tile
#define MAXTILES (NSLOTS / TS + NEXP)   // 4104

// ---------------- device scratch ----------------
__device__ float g_yscat[(size_t)NSLOTS * D];    // gated per-slot outputs (256 MiB)
__device__ uint4 g_whp[NEXP * 2048];             // W hi bf16, packed [e][out][k] (32KB/expert)
__device__ uint4 g_wlp[NEXP * 2048];             // W lo bf16, packed
__device__ int   g_seg[NEXP + 1];
__device__ int   g_tile_e[MAXTILES];
__device__ int   g_tile_s[MAXTILES];
__device__ int   g_ntiles;

// ---------------- helpers ----------------
__device__ __forceinline__ uint32_t smem_u32(const void* p) {
    uint32_t a;
    asm("{ .reg .u64 t; cvta.to.shared.u64 t, %1; cvt.u32.u64 %0, t; }" : "=r"(a) : "l"(p));
    return a;
}
__device__ __forceinline__ void ldsm_x4(uint32_t* r, uint32_t addr) {
    asm volatile("ldmatrix.sync.aligned.m8n8.x4.shared.b16 {%0,%1,%2,%3}, [%4];"
        : "=r"(r[0]), "=r"(r[1]), "=r"(r[2]), "=r"(r[3]) : "r"(addr));
}
__device__ __forceinline__ void mma_bf16(float* c, const uint32_t* a, uint32_t b0, uint32_t b1) {
    asm volatile("mma.sync.aligned.m16n8k16.row.col.f32.bf16.bf16.f32 "
        "{%0,%1,%2,%3}, {%4,%5,%6,%7}, {%8,%9}, {%0,%1,%2,%3};"
        : "+f"(c[0]), "+f"(c[1]), "+f"(c[2]), "+f"(c[3])
        : "r"(a[0]), "r"(a[1]), "r"(a[2]), "r"(a[3]), "r"(b0), "r"(b1));
}
#define CP_ASYNC16(dst, src) \
    asm volatile("cp.async.cg.shared.global [%0], [%1], 16;" :: "r"(dst), "l"(src))
#define CP_COMMIT()  asm volatile("cp.async.commit_group;" ::: "memory")
#define CP_WAIT0()   asm volatile("cp.async.wait_group 0;" ::: "memory")

// convert 8 fp32 -> hi/lo bf16 packs (16 B each)
__device__ __forceinline__ void cvt8(const float* v, uint4& hv, uint4& lv) {
    __nv_bfloat16 h[8]; float l[8];
#pragma unroll
    for (int i = 0; i < 8; i++) {
        h[i] = __float2bfloat16_rn(v[i]);
        l[i] = v[i] - __bfloat162float(h[i]);
    }
    uint32_t hu[4], lu[4];
#pragma unroll
    for (int i = 0; i < 4; i++) {
        __nv_bfloat162 hp = __halves2bfloat162(h[2 * i], h[2 * i + 1]);
        hu[i] = *reinterpret_cast<uint32_t*>(&hp);
        __nv_bfloat162 lp = __floats2bfloat162_rn(l[2 * i], l[2 * i + 1]);
        lu[i] = *reinterpret_cast<uint32_t*>(&lp);
    }
    hv = make_uint4(hu[0], hu[1], hu[2], hu[3]);
    lv = make_uint4(lu[0], lu[1], lu[2], lu[3]);
}

// -------------------------------------------------------------------
// Prologue 1: weight fp32 [E, d_out, d_in] -> packed bf16 hi/lo
// -------------------------------------------------------------------
__global__ void wconv_kernel(const float* __restrict__ w) {
    int e = blockIdx.x;
    int tid = threadIdx.x;
    int row = tid >> 1;
    int half = tid & 1;
    const float* wr = w + ((size_t)e * D + row) * D;
    uint4* whe = g_whp + e * 2048;
    uint4* wle = g_wlp + e * 2048;
#pragma unroll
    for (int g = 0; g < 8; g++) {
        int col0 = half * 64 + g * 8;
        float v[8];
#pragma unroll
        for (int i = 0; i < 8; i++) v[i] = wr[col0 + i];
        uint4 hv, lv;
        cvt8(v, hv, lv);
        int idx = row * 16 + half * 8 + g;
        whe[idx] = hv;
        wle[idx] = lv;
    }
}

// -------------------------------------------------------------------
// Prologue 2: expert segments + dense tile map
// -------------------------------------------------------------------
__global__ void seg_kernel(const int* __restrict__ sei) {
    __shared__ int seg[NEXP + 1];
    __shared__ int cnts[NEXP];
    int t = threadIdx.x;
    if (t <= NEXP) {
        int lo = 0, hi = NSLOTS;
        while (lo < hi) {
            int mid = (lo + hi) >> 1;
            if (sei[mid] < t) lo = mid + 1; else hi = mid;
        }
        seg[t] = lo;
        g_seg[t] = lo;
    }
    __syncthreads();
    if (t < NEXP) cnts[t] = (seg[t + 1] - seg[t] + TS - 1) / TS;
    __syncthreads();
    if (t < NEXP) {
        int off = 0;
        for (int i = 0; i < t; i++) off += cnts[i];
        int s = seg[t];
        for (int i = 0; i < cnts[t]; i++) {
            g_tile_e[off + i] = t;
            g_tile_s[off + i] = s + i * TS;
        }
    }
    if (t == 0) {
        int tot = 0;
        for (int i = 0; i < NEXP; i++) tot += cnts[i];
        g_ntiles = tot;
    }
}

// -------------------------------------------------------------------
// SMEM layout
// -------------------------------------------------------------------
#define XROWB 272
#define IMGB  (128 * XROWB)          // 34816
#define RAWS  528                    // raw fp32 row stride (bytes)
#define RAWB  (128 * RAWS)           // 67584
#define OFF_SHF 0
#define OFF_SHG 512
#define OFF_RAW 1024
#define OFF_XH  (OFF_RAW + RAWB)     // 68608
#define OFF_XL  (OFF_XH + IMGB)
#define OFF_WH  (OFF_XL + IMGB)
#define OFF_WL  (OFF_WH + IMGB)
#define SMEM_TOTAL (OFF_WL + IMGB)   // 207872

// issue cp.async gather of one X row-half per thread (16 x 16B)
__device__ __forceinline__ void issue_x(const float* __restrict__ x, int tok,
                                        int tid, uint32_t sb) {
    uint32_t dst = sb + OFF_RAW + (uint32_t)(tid >> 1) * RAWS + (tid & 1) * 256;
    const char* src = (const char*)(x + (size_t)tok * D) + (tid & 1) * 256;
#pragma unroll
    for (int c = 0; c < 16; c++)
        CP_ASYNC16(dst + c * 16, src + c * 16);
}

// -------------------------------------------------------------------
// Main: persistent bf16-split HMMA GEMM, W reuse + cp.async X pipeline
// -------------------------------------------------------------------
extern "C" __global__ void __launch_bounds__(256, 1)
moe_mma_kernel(const float* __restrict__ x,
               const float* __restrict__ gates,
               const int*   __restrict__ ssi) {
    int ntiles = g_ntiles;
    int nc = gridDim.x;
    int per = ntiles / nc, rem = ntiles % nc;
    int t0 = blockIdx.x * per + min((int)blockIdx.x, rem);
    int t1 = t0 + per + (blockIdx.x < rem ? 1 : 0);
    if (t0 >= t1) return;

    extern __shared__ char smem[];
    uint32_t sb = smem_u32(smem);
    int*   sh_f = (int*)(smem + OFF_SHF);
    float* sh_g = (float*)(smem + OFF_SHG);

    int tid = threadIdx.x;
    int wid = tid >> 5;
    int lane = tid & 31;
    int r = tid >> 1;                 // row this thread stages

    // warp tile coords (fixed)
    int wr = wid & 3;
    int wc = wid >> 2;
    int lrow = (lane & 7) | (lane & 8);
    int kby  = (lane >> 4) * 16;
    uint32_t aA = sb + OFF_XH + (uint32_t)(wr * 32 + lrow) * XROWB + kby;
    uint32_t aB = sb + OFF_WH + (uint32_t)(wc * 64 + lrow) * XROWB + kby;
    const uint32_t DL = IMGB;

    // ---- prime tile t0 ----
    int e  = g_tile_e[t0];
    int s0 = g_tile_s[t0];
    int cnt = min(TS, g_seg[e + 1] - s0);
    int   fcur = (r < cnt) ? ssi[s0 + r] : 0;
    float gcur = (r < cnt) ? gates[fcur] : 0.f;
    issue_x(x, fcur >> 1, tid, sb);   // TOPK == 2
    CP_COMMIT();

    int staged_e = -1;

    for (int t = t0; t < t1; t++) {
        // ---- prefetch metadata for t+1 (latency hidden under convert/MMA) ----
        bool havenext = (t + 1 < t1);
        int en = e, s0n = s0, cntn = cnt, fnxt = 0; float gnxt = 0.f;
        if (havenext) {
            en  = g_tile_e[t + 1];
            s0n = g_tile_s[t + 1];
            cntn = min(TS, g_seg[en + 1] - s0n);
            fnxt = (r < cntn) ? ssi[s0n + r] : 0;
            gnxt = (r < cntn) ? gates[fnxt] : 0.f;
        }

        CP_WAIT0();            // raw(t) resident
        __syncthreads();       // publish raw; MMA(t-1)+scatter(t-1) done

        // ---- stage W on expert change (rare) ----
        if (e != staged_e) {
            const uint4* whe = g_whp + e * 2048;
            const uint4* wle = g_wlp + e * 2048;
#pragma unroll
            for (int i = 0; i < 8; i++) {
                int cid = tid + 256 * i;
                int row = cid >> 4;
                int w16 = cid & 15;
                uint32_t doff = row * XROWB + w16 * 16;
                *(uint4*)(smem + OFF_WH + doff) = whe[cid];
                *(uint4*)(smem + OFF_WL + doff) = wle[cid];
            }
            staged_e = e;
        }

        // ---- metadata to smem ----
        if (!(tid & 1)) {
            sh_f[r] = fcur;
            sh_g[r] = gcur;
        }

        // ---- convert raw fp32 -> bf16 hi/lo images ----
        {
            int half = tid & 1;
            const char* rp = smem + OFF_RAW + (uint32_t)r * RAWS + half * 256;
            char* xh = smem + OFF_XH;
            char* xl = smem + OFF_XL;
#pragma unroll
            for (int g = 0; g < 8; g++) {
                float4 a = *(const float4*)(rp + g * 32);
                float4 b = *(const float4*)(rp + g * 32 + 16);
                float v[8] = {a.x, a.y, a.z, a.w, b.x, b.y, b.z, b.w};
                uint4 hv, lv;
                cvt8(v, hv, lv);
                uint32_t off = (uint32_t)r * XROWB + (half * 64 + g * 8) * 2;
                *(uint4*)(xh + off) = hv;
                *(uint4*)(xl + off) = lv;
            }
        }
        __syncthreads();       // images + meta ready; raw drained

        // ---- kick gather for t+1 (overlaps with MMA below) ----
        if (havenext) {
            issue_x(x, fnxt >> 1, tid, sb);
            CP_COMMIT();
        }

        // ---- MMA: 3-term bf16 split ----
        float acc[2][8][4];
#pragma unroll
        for (int mt = 0; mt < 2; mt++)
#pragma unroll
            for (int nt = 0; nt < 8; nt++)
#pragma unroll
                for (int i = 0; i < 4; i++) acc[mt][nt][i] = 0.f;

#pragma unroll
        for (int kk = 0; kk < 8; kk++) {
            uint32_t kb = kk * 32;
            uint32_t ah[2][4], al[2][4];
            ldsm_x4(ah[0], aA + kb);
            ldsm_x4(ah[1], aA + 16 * XROWB + kb);
            ldsm_x4(al[0], aA + DL + kb);
            ldsm_x4(al[1], aA + DL + 16 * XROWB + kb);
#pragma unroll
            for (int ng = 0; ng < 4; ng++) {
                uint32_t bh[4], bl[4];
                ldsm_x4(bh, aB + ng * 16 * XROWB + kb);
                ldsm_x4(bl, aB + DL + ng * 16 * XROWB + kb);
#pragma unroll
                for (int mt = 0; mt < 2; mt++) {
                    mma_bf16(acc[mt][2 * ng],     ah[mt], bh[0], bh[2]);
                    mma_bf16(acc[mt][2 * ng + 1], ah[mt], bh[1], bh[3]);
                    mma_bf16(acc[mt][2 * ng],     al[mt], bh[0], bh[2]);
                    mma_bf16(acc[mt][2 * ng + 1], al[mt], bh[1], bh[3]);
                    mma_bf16(acc[mt][2 * ng],     ah[mt], bl[0], bl[2]);
                    mma_bf16(acc[mt][2 * ng + 1], ah[mt], bl[1], bl[3]);
                }
            }
        }

        // ---- epilogue: gate + scatter ----
        {
            int row_lo = lane >> 2;
            int col0 = wc * 64 + (lane & 3) * 2;
#pragma unroll
            for (int mt = 0; mt < 2; mt++) {
                int ja = wr * 32 + mt * 16 + row_lo;
                int jb = ja + 8;
                bool oka = ja < cnt, okb = jb < cnt;
                float ga = sh_g[ja], gb = sh_g[jb];
                float* da = g_yscat + (size_t)sh_f[ja] * D + col0;
                float* db = g_yscat + (size_t)sh_f[jb] * D + col0;
#pragma unroll
                for (int nt = 0; nt < 8; nt++) {
                    if (oka) {
                        float2 v = make_float2(acc[mt][nt][0] * ga, acc[mt][nt][1] * ga);
                        *(float2*)(da + nt * 8) = v;
                    }
                    if (okb) {
                        float2 v = make_float2(acc[mt][nt][2] * gb, acc[mt][nt][3] * gb);
                        *(float2*)(db + nt * 8) = v;
                    }
                }
            }
        }

        // rotate tile state
        e = en; s0 = s0n; cnt = cntn; fcur = fnxt; gcur = gnxt;
    }
}

// -------------------------------------------------------------------
// combine: out[n] = y[2n] + y[2n+1]  (at DRAM roofline)
// -------------------------------------------------------------------
__global__ void combine_kernel(float* __restrict__ out) {
    size_t idx = (size_t)blockIdx.x * blockDim.x + threadIdx.x;
    const float4* y4 = (const float4*)g_yscat;
    size_t n = idx >> 5;
    int d4 = (int)(idx & 31);
    float4 a = y4[n * 64 + d4];
    float4 b = y4[n * 64 + 32 + d4];
    ((float4*)out)[idx] = make_float4(a.x + b.x, a.y + b.y, a.z + b.z, a.w + b.w);
}

// -------------------------------------------------------------------
extern "C" void kernel_launch(void* const* d_in, const int* in_sizes, int n_in,
                              void* d_out, int out_size) {
    const float* inputs = (const float*)d_in[0];
    const float* weight = (const float*)d_in[1];
    const float* gates  = (const float*)d_in[2];
    const int*   sei    = (const int*)d_in[4];
    const int*   ssi    = (const int*)d_in[5];
    float* out = (float*)d_out;

    int nsm = 148;
    cudaDeviceGetAttribute(&nsm, cudaDevAttrMultiProcessorCount, 0);

    cudaFuncSetAttribute(moe_mma_kernel,
                         cudaFuncAttributeMaxDynamicSharedMemorySize, SMEM_TOTAL);

    wconv_kernel<<<NEXP, 256>>>(weight);
    seg_kernel<<<1, 32>>>(sei);

    moe_mma_kernel<<<nsm, 256, SMEM_TOTAL>>>(inputs, gates, ssi);

    combine_kernel<<<(N_TOK * D / 4) / 256, 256>>>(out);
}